// round 16
// baseline (speedup 1.0000x reference)
#include <cuda_runtime.h>
#include <cuda_fp16.h>
#include <cstdint>

#define BB 2
#define TT 512
#define CC 128
#define C2 256
#define HS 64

// ---------------- scratch (no allocations allowed) -------------------------
__device__ float g_K[BB*TT*CC];
__device__ float g_Q[BB*TT*CC];
__device__ float g_V[BB*TT*HS];
__device__ float g_S[(size_t)BB*TT*TT];
__device__ int   g_cnt[TT];
// W1^T (n-major) fp16, swizzled: 4 K-chunks x 16KB
__device__ __align__(16) unsigned char g_Bimg[4*16384];

__device__ __forceinline__ uint32_t smem_u32(const void* p) {
    uint32_t a;
    asm("{ .reg .u64 t; cvta.to.shared.u64 t, %1; cvt.u32.u64 %0, t; }" : "=r"(a) : "l"(p));
    return a;
}
// row-local swizzle: rows are 128B; XOR 16B-bank by (row&7)
#define SWZB(row, kbyte) ((uint32_t)(row)*128u + (((uint32_t)(kbyte)) ^ ((((uint32_t)(row))&7u)*16u)))

__device__ __forceinline__ void ldsm_x4(uint32_t addr, uint32_t& r0, uint32_t& r1,
                                        uint32_t& r2, uint32_t& r3) {
    asm volatile("ldmatrix.sync.aligned.m8n8.x4.shared.b16 {%0,%1,%2,%3}, [%4];"
                 : "=r"(r0), "=r"(r1), "=r"(r2), "=r"(r3) : "r"(addr));
}
// fp16-accumulate HMMA (2 output regs = 4 halves)
__device__ __forceinline__ void mma16816h(uint32_t* d, const uint32_t* a, uint32_t b0, uint32_t b1) {
    asm volatile("mma.sync.aligned.m16n8k16.row.col.f16.f16.f16.f16 "
                 "{%0,%1}, {%2,%3,%4,%5}, {%6,%7}, {%0,%1};"
                 : "+r"(d[0]), "+r"(d[1])
                 : "r"(a[0]), "r"(a[1]), "r"(a[2]), "r"(a[3]), "r"(b0), "r"(b1));
}
// exact gelu via erff (cheap polynomial, no exp path)
__device__ __forceinline__ float gelu_exact(float x) {
    return 0.5f * x * (1.f + erff(x * 0.70710678118654752f));
}

// ---------------------------------------------------------------------------
// Kernel 1: blocks [0,512): K/Q/V (2 rows each, role-split threads).
//           blocks [512,640): W1 fp16 image.  Block 512 also resets g_cnt.
// ---------------------------------------------------------------------------
__global__ void kqv_prep_kernel(const float* __restrict__ x,
                                const float* __restrict__ W1,
                                const float* __restrict__ Wv,
                                const float* __restrict__ bv) {
    if (blockIdx.x >= 512) {
        if (blockIdx.x == 512) {
            g_cnt[threadIdx.x]       = 0;
            g_cnt[threadIdx.x + 256] = 0;
        }
        int t = (blockIdx.x - 512) * 256 + threadIdx.x;   // 0 .. 32767
        int c   = t >> 13;
        int rem = t & 8191;
        int n   = rem >> 6;
        int kk  = rem & 63;
        float w = W1[(c*64 + kk) * CC + n];
        *(__half*)(g_Bimg + c*16384 + SWZB(n, kk*2)) = __float2half_rn(w);
        return;
    }

    __shared__ float sx[2][CC];
    int r0 = blockIdx.x * 2;
    int t = threadIdx.x;
    if (t < 2*CC)
        sx[t >> 7][t & 127] = x[(r0 + (t >> 7))*CC + (t & 127)];
    __syncthreads();

    if (t < 128) {
        int h0 = (t & 63) * 2;
        const float* Wcol = (t < 64) ? W1 : (W1 + CC*CC);
        float a00 = 0.f, a01 = 0.f, a10 = 0.f, a11 = 0.f;
#pragma unroll 8
        for (int d = 0; d < CC; d++) {
            float2 w = *(const float2*)&Wcol[d*CC + h0];
            float x0 = sx[0][d], x1 = sx[1][d];
            a00 = fmaf(x0, w.x, a00);
            a01 = fmaf(x0, w.y, a01);
            a10 = fmaf(x1, w.x, a10);
            a11 = fmaf(x1, w.y, a11);
        }
        float* dst = (t < 64) ? g_K : g_Q;
        *(float2*)&dst[(r0    )*CC + h0] = make_float2(a00, a01);
        *(float2*)&dst[(r0 + 1)*CC + h0] = make_float2(a10, a11);
    } else if (t < 192) {
        int hv = t - 128;
        float bvh = bv[hv];
        float v0 = bvh, v1 = bvh;
#pragma unroll 8
        for (int d = 0; d < CC; d++) {
            float w = Wv[d*HS + hv];
            v0 = fmaf(sx[0][d], w, v0);
            v1 = fmaf(sx[1][d], w, v1);
        }
        g_V[(r0    )*HS + hv] = v0;
        g_V[(r0 + 1)*HS + hv] = v1;
    }
}

// ---------------------------------------------------------------------------
// Kernel 2: fp16 HMMA P-GEMM + erff gelu epilogue + FUSED softmax/AV
//   (last block per row i runs softmax + wei@V in dead smem)
// ---------------------------------------------------------------------------
#define B0_OFF 0
#define B1_OFF 16384
#define A0_OFF 32768
#define A1_OFF 40960
#define MISC   49152
#define SMEM_BYTES (MISC + 4096)

__global__ void __launch_bounds__(128, 4)
score_kernel(const float* __restrict__ pd,
             const float* __restrict__ b1,
             const float* __restrict__ W2,
             const float* __restrict__ b2,
             float* __restrict__ out) {
    int i = blockIdx.x;
    int jbase = blockIdx.y * 64;
    if (jbase > i) return;
    int jmax = (i - jbase < 64) ? (i - jbase) : 63;

    extern __shared__ __align__(16) unsigned char sm[];
    __shared__ int s_last;
    uint32_t base = smem_u32(sm);

    int tid  = threadIdx.x;
    int lane = tid & 31;
    int wid  = tid >> 5;
    int warp_j = wid & 1;    // 2 x 32 rows
    int warp_n = wid >> 1;   // 2 x 64 cols
    bool active = (warp_j * 32 <= jmax);
    bool act1   = (warp_j * 32 + 16 <= jmax);   // second 16-row subtile

    float* w2s   = (float*)(sm + MISC);          // 128 f
    float* qs    = (float*)(sm + MISC + 512);    // 2x128 f
    float* partS = (float*)(sm + MISC + 1536);   // 256 f
    float* b2s   = (float*)(sm + MISC + 2560);

    {
        w2s[tid] = W2[tid];
        float b1h = b1[tid];
        qs[tid]       = g_Q[((size_t)i)*CC + tid]        + b1h;
        qs[128 + tid] = g_Q[((size_t)(TT + i))*CC + tid] + b1h;
        if (tid == 0) b2s[0] = b2[0];
    }

    const float4* prow = (const float4*)(pd + ((size_t)i*TT + jbase)*C2);

#define COPY_B(c, bbuf)                                                         \
    do {                                                                        \
        const float4* src = (const float4*)(g_Bimg + (c)*16384);                \
        float4* dst = (float4*)(sm + (bbuf));                                   \
        _Pragma("unroll")                                                       \
        for (int it = 0; it < 8; it++) dst[tid + it*128] = src[tid + it*128];   \
    } while (0)

#define CONVERT_A(c, abuf)                                                      \
    do {                                                                        \
        _Pragma("unroll")                                                       \
        for (int it = 0; it < 8; it++) {                                        \
            int idx = tid + it*128;          /* 0..1023 */                      \
            int j   = idx >> 4;                                                 \
            int f4  = idx & 15;                                                 \
            if (j <= jmax) {                                                    \
                float4 v = __ldcs(prow + j*64 + (c)*16 + f4);                   \
                __half2 p0 = __floats2half2_rn(v.x, v.y);                       \
                __half2 p1 = __floats2half2_rn(v.z, v.w);                       \
                unsigned long long h64 =                                        \
                      (unsigned long long)(*(uint32_t*)&p0)                     \
                    | ((unsigned long long)(*(uint32_t*)&p1) << 32);            \
                *(unsigned long long*)(sm + (abuf) + SWZB(j, f4*8)) = h64;      \
            }                                                                   \
        }                                                                       \
    } while (0)

    uint32_t acc16[2][8][2];
#pragma unroll
    for (int jt2 = 0; jt2 < 2; jt2++)
#pragma unroll
        for (int nt = 0; nt < 8; nt++) { acc16[jt2][nt][0] = 0u; acc16[jt2][nt][1] = 0u; }

    COPY_B(0, B0_OFF);
    CONVERT_A(0, A0_OFF);
    __syncthreads();

#pragma unroll
    for (int c = 0; c < 4; c++) {
        uint32_t aCur = (c & 1) ? A1_OFF : A0_OFF;
        uint32_t bCur = (c & 1) ? B1_OFF : B0_OFF;
        if (c < 3) {
            uint32_t aNext = (c & 1) ? A0_OFF : A1_OFF;
            uint32_t bNext = (c & 1) ? B0_OFF : B1_OFF;
            COPY_B(c + 1, bNext);
            CONVERT_A(c + 1, aNext);
        }

        if (active) {
            uint32_t bBase = base + bCur;
#pragma unroll
            for (int kk = 0; kk < 4; kk++) {
                int k0 = kk*16;
                uint32_t a0[4], a1[4];
                {
                    uint32_t kb = (uint32_t)(k0 + ((lane >> 4) & 1)*8)*2u;
                    int j0 = warp_j*32 + (lane & 15);
                    ldsm_x4(base + aCur + SWZB(j0, kb), a0[0], a0[1], a0[2], a0[3]);
                    if (act1) {
                        int j1 = j0 + 16;
                        ldsm_x4(base + aCur + SWZB(j1, kb), a1[0], a1[1], a1[2], a1[3]);
                    }
                }
#pragma unroll
                for (int p = 0; p < 4; p++) {
                    int n = warp_n*64 + p*16 + (lane & 7) + ((lane >> 4) << 3);
                    uint32_t kb = (uint32_t)(k0 + ((lane >> 3) & 1)*8)*2u;
                    uint32_t b0, b1r, b2r, b3;
                    ldsm_x4(bBase + SWZB(n, kb), b0, b1r, b2r, b3);
                    mma16816h(acc16[0][2*p],   a0, b0,  b1r);
                    mma16816h(acc16[0][2*p+1], a0, b2r, b3);
                    if (act1) {
                        mma16816h(acc16[1][2*p],   a1, b0,  b1r);
                        mma16816h(acc16[1][2*p+1], a1, b2r, b3);
                    }
                }
            }
        }
        __syncthreads();
    }

    if (active) {
#pragma unroll
        for (int jt2 = 0; jt2 < 2; jt2++) {
            if (jt2 == 1 && !act1) continue;
#pragma unroll
            for (int rh = 0; rh < 2; rh++) {
                int j = warp_j*32 + jt2*16 + (lane >> 2) + 8*rh;
                float2 av[8];
#pragma unroll
                for (int nt = 0; nt < 8; nt++)
                    av[nt] = __half22float2(*(__half2*)&acc16[jt2][nt][rh]);
#pragma unroll
                for (int b = 0; b < BB; b++) {
                    const float* qb = qs + b*128;
                    const float* kb = g_K + ((size_t)(b*TT + jbase + j))*CC;
                    float partial = 0.f;
#pragma unroll
                    for (int nt = 0; nt < 8; nt++) {
                        int h0 = warp_n*64 + nt*8 + (lane & 3)*2;
                        float2 kv = *(const float2*)(kb + h0);
                        float pre0 = av[nt].x + qb[h0]     + kv.x;
                        float pre1 = av[nt].y + qb[h0 + 1] + kv.y;
                        partial = fmaf(gelu_exact(pre0), w2s[h0],     partial);
                        partial = fmaf(gelu_exact(pre1), w2s[h0 + 1], partial);
                    }
                    partial += __shfl_xor_sync(0xffffffffu, partial, 1);
                    partial += __shfl_xor_sync(0xffffffffu, partial, 2);
                    if ((lane & 3) == 0)
                        partS[warp_n*128 + b*64 + j] = partial;
                }
            }
        }
    }
    __syncthreads();

    {
        int b = tid >> 6, j = tid & 63;
        int jg = jbase + j;
        if (jg <= i)
            g_S[((size_t)(b*TT + i))*TT + jg] =
                partS[b*64 + j] + partS[128 + b*64 + j] + b2s[0];
    }

    // ---- row-completion: last block for row i does softmax + AV ----
    __threadfence();
    if (tid == 0) {
        int old = atomicAdd(&g_cnt[i], 1);
        s_last = (old == (i >> 6)) ? 1 : 0;    // ntiles(i) = i/64 + 1
    }
    __syncthreads();
    if (!s_last) return;
    __threadfence();

    float* p    = (float*)sm;             // 512 f (dead A/B buffers)
    float* redw = (float*)(sm + 2048);    // 4 f
    float* red2 = (float*)(sm + 2176);    // 128 f
    const float scale = 0.088388347648318447f;
    int n = i + 1;

#pragma unroll
    for (int b = 0; b < BB; b++) {
        const float* srow = &g_S[((size_t)(b*TT + i))*TT];

        float m = -1e30f;
        for (int j = tid; j < n; j += 128) m = fmaxf(m, srow[j]);
#pragma unroll
        for (int off = 16; off; off >>= 1)
            m = fmaxf(m, __shfl_xor_sync(0xffffffffu, m, off));
        if (lane == 0) redw[wid] = m;
        __syncthreads();
        m = fmaxf(fmaxf(redw[0], redw[1]), fmaxf(redw[2], redw[3]));

        float sum = 0.f;
        for (int j = tid; j < n; j += 128) {
            float e = expf((srow[j] - m) * scale);
            p[j] = e;
            sum += e;
        }
#pragma unroll
        for (int off = 16; off; off >>= 1)
            sum += __shfl_xor_sync(0xffffffffu, sum, off);
        if (lane == 0) redw[wid] = sum;
        __syncthreads();
        float inv = 1.f / (redw[0] + redw[1] + redw[2] + redw[3]);

        // AV: h = tid&63, 2 slices x 2 accumulators
        int h = tid & 63, slice = tid >> 6;
        const float* vb = g_V + (size_t)b*TT*HS + h;
        float a0 = 0.f, a1 = 0.f;
        int j = slice;
        for (; j + 2 < n; j += 4) {
            a0 = fmaf(p[j],     vb[(size_t)j*HS],       a0);
            a1 = fmaf(p[j + 2], vb[(size_t)(j + 2)*HS], a1);
        }
        if (j < n) a0 = fmaf(p[j], vb[(size_t)j*HS], a0);
        red2[tid] = a0 + a1;
        __syncthreads();
        if (tid < HS)
            out[((size_t)(b*TT + i))*HS + tid] = (red2[tid] + red2[tid + 64]) * inv;
        __syncthreads();   // before p/red reuse in next batch
    }
}

// ---------------------------------------------------------------------------
extern "C" void kernel_launch(void* const* d_in, const int* in_sizes, int n_in,
                              void* d_out, int out_size) {
    const float* x  = (const float*)d_in[0];
    const float* pd = (const float*)d_in[2];
    const float* W1 = (const float*)d_in[3];
    const float* b1 = (const float*)d_in[4];
    const float* W2 = (const float*)d_in[5];
    const float* b2 = (const float*)d_in[6];
    const float* Wv = (const float*)d_in[7];
    const float* bv = (const float*)d_in[8];
    float* out = (float*)d_out;

    cudaFuncSetAttribute(score_kernel, cudaFuncAttributeMaxDynamicSharedMemorySize, SMEM_BYTES);

    kqv_prep_kernel<<<640, 256>>>(x, W1, Wv, bv);
    score_kernel<<<dim3(TT, 8), 128, SMEM_BYTES>>>(pd, b1, W2, b2, out);
}